// round 14
// baseline (speedup 1.0000x reference)
#include <cuda_runtime.h>
#include <cuda_bf16.h>

#define NMAX 50000
#define EMAX 800000
#define F 128
#define EFD 6
#define SCAN_T 256

// ---- packed dual-fp32 ops (Blackwell f32x2) --------------------------------
#define PACK_F32X2(d, a, b) \
    asm("mov.b64 %0, {%1, %2};" : "=l"(d) : "f"(a), "f"(b))
#define FMA_F32X2(d, a, b, c) \
    asm("fma.rn.f32x2 %0, %1, %2, %3;" : "=l"(d) : "l"(a), "l"(b), "l"(c))
#define ADD_F32X2(d, a, b) \
    asm("add.rn.f32x2 %0, %1, %2;" : "=l"(d) : "l"(a), "l"(b))
#define UNPACK_F32X2(lo, hi, v) \
    asm("mov.b64 {%0, %1}, %2;" : "=f"(lo), "=f"(hi) : "l"(v))

// ---------------- device scratch ----------------
__device__ int    g_counts[NMAX];
__device__ int    g_cursor[NMAX];
__device__ int    g_rowptr[NMAX];     // region start (NOT globally monotonic)
__device__ int    g_rowend[NMAX];     // region end
__device__ int    g_src[EMAX];
__device__ int    g_dst[EMAX];
__device__ int    g_edges[EMAX];      // src only
__device__ float4 g_aggX[NMAX * (F / 4)];
__device__ float4 g_aggE4[NMAX * 2];  // padded 8 floats/node; re-zeroed by k5
__device__ int    g_total;            // tile-base allocator (reset in k1)

// ---------------- K1: decode + histogram + eF vector-atomic aggregation -----
__global__ void __launch_bounds__(256)
k1_decode_hist(const void* __restrict__ ei, const float* __restrict__ eF,
               int N, int E) {
    __shared__ int s_is64;
    int t = threadIdx.x;
    if (t < 32) {
        const long long* p = (const long long*)ei;
        long long nwords = (long long)E * 2;
        int bad = 0;
        #pragma unroll
        for (int j = 0; j < 4; j++) {
            long long idx = t + j * 32;
            if (idx < nwords) {
                long long v = p[idx];
                if (v < 0 || v >= (long long)N) bad = 1;
            }
        }
        unsigned m = __ballot_sync(0xffffffffu, bad);
        if (t == 0) s_is64 = (m == 0u) ? 1 : 0;
    }
    __syncthreads();

    int e = blockIdx.x * blockDim.x + t;
    if (blockIdx.x == 0 && t == 0) g_total = 0;
    if (e >= E) return;
    int s, d;
    if (s_is64) {
        const longlong2* p = (const longlong2*)ei;
        longlong2 v = p[e];
        s = (int)v.x; d = (int)v.y;
    } else {
        const int2* p = (const int2*)ei;
        int2 v = p[e];
        s = v.x; d = v.y;
    }
    g_src[e] = s;
    g_dst[e] = d;
    atomicAdd(&g_counts[d], 1);

    const float2* ef2 = (const float2*)(eF + (long)e * EFD);
    float2 f0 = ef2[0], f1 = ef2[1], f2 = ef2[2];
    float* base = (float*)&g_aggE4[d * 2];
    atomicAdd((float4*)base, make_float4(f0.x, f0.y, f1.x, f1.y));
    atomicAdd((float2*)(base + 4), f2);
}

// ---------------- K2: single-kernel scan (atomic tile base) + re-zero -------
__global__ void __launch_bounds__(SCAN_T)
k2_scan(int N) {
    __shared__ int ws[8];
    __shared__ int s_base;
    int t = threadIdx.x, lane = t & 31, wid = t >> 5;
    int i = blockIdx.x * SCAN_T + t;
    int v = (i < N) ? g_counts[i] : 0;

    int x = v;
    #pragma unroll
    for (int o = 1; o < 32; o <<= 1) {
        int y = __shfl_up_sync(0xffffffffu, x, o);
        if (lane >= o) x += y;
    }
    if (lane == 31) ws[wid] = x;
    __syncthreads();
    if (wid == 0 && lane < 8) {
        int y = ws[lane];
        #pragma unroll
        for (int o = 1; o < 8; o <<= 1) {
            int z = __shfl_up_sync(0x000000ffu, y, o);
            if (lane >= o) y += z;
        }
        ws[lane] = y;
    }
    __syncthreads();
    int incl = x + (wid > 0 ? ws[wid - 1] : 0);

    if (t == 0) s_base = atomicAdd(&g_total, ws[7]);
    __syncthreads();

    if (i < N) {
        int start = s_base + incl - v;
        g_rowptr[i] = start;
        g_rowend[i] = start + v;
        g_cursor[i] = start;
        g_counts[i] = 0;
    }
}

// ---------------- K3: scatter src into CSR slots (MLP=8, 4B payload) --------
__global__ void __launch_bounds__(256)
k3_scatter(int E) {
    int e0 = (blockIdx.x * blockDim.x + threadIdx.x) * 8;
    int d[8], s[8];
    #pragma unroll
    for (int j = 0; j < 8; j++) {
        int e = e0 + j;
        if (e < E) { d[j] = g_dst[e]; s[j] = g_src[e]; }
    }
    #pragma unroll
    for (int j = 0; j < 8; j++) {
        int e = e0 + j;
        if (e < E) {
            int p = atomicAdd(&g_cursor[d[j]], 1);
            g_edges[p] = s[j];
        }
    }
}

// ---------------- K4: warp-per-node aggregation (unroll 16) -----------------
__global__ void __launch_bounds__(256)
k4_aggregate(const ulonglong2* __restrict__ X2, int N) {
    int gwarp = (blockIdx.x * blockDim.x + threadIdx.x) >> 5;
    int lane  = threadIdx.x & 31;
    if (gwarp >= N) return;
    int v = gwarp;
    int s0 = g_rowptr[v], s1 = g_rowend[v];
    unsigned long long a01 = 0ULL, a23 = 0ULL;
    for (int base = s0; base < s1; base += 32) {
        int cnt = s1 - base; if (cnt > 32) cnt = 32;
        int sc = g_edges[base + (lane < cnt ? lane : 0)];   // coalesced chunk
        for (int j = 0; j < cnt; j += 16) {
            #pragma unroll
            for (int u = 0; u < 16; u++) {
                if (j + u < cnt) {  // uniform across warp
                    int sj = __shfl_sync(0xffffffffu, sc, j + u);
                    ulonglong2 xv = X2[(long)sj * 32 + lane];
                    ADD_F32X2(a01, a01, xv.x);
                    ADD_F32X2(a23, a23, xv.y);
                }
            }
        }
    }
    ulonglong2 outv; outv.x = a01; outv.y = a23;
    *(ulonglong2*)&g_aggX[(long)v * 32 + lane] = outv;
}

// ---------------- K5: persistent f32x2 GEMM, 2 CTAs/SM ----------------------
#define K5_THREADS 256
#define K5W (K5_THREADS / 32)   // 8 warps
#define K5_RPW 8
#define K5_BLOCKS 296           // 2 per SM
// smem: Wp 64KB | Wes 3KB | bsum 0.5KB | xs 8w*8r*32*16 = 32KB  ~= 99.75KB
#define K5_SMEM (F * 32 * 16 + EFD * F * 4 + F * 4 + K5W * K5_RPW * 32 * 16)

__global__ void __launch_bounds__(K5_THREADS)
k5_final(const float4* __restrict__ W4, const float* __restrict__ b,
         const float* __restrict__ We, const float* __restrict__ be,
         float* __restrict__ out, int N) {
    extern __shared__ char smem[];
    ulonglong2* Wp   = (ulonglong2*)smem;
    float*      Wes  = (float*)(smem + F * 32 * 16);
    float*      bsum = Wes + EFD * F;
    float4*     xs   = (float4*)(bsum + F);

    int tid = threadIdx.x, warp = tid >> 5, lane = tid & 31;

    for (int idx = tid; idx < F * 32; idx += K5_THREADS) {
        float4 w4 = __ldg(&W4[idx]);
        ulonglong2 p;
        PACK_F32X2(p.x, w4.x, w4.y);
        PACK_F32X2(p.y, w4.z, w4.w);
        Wp[idx] = p;
    }
    for (int i = tid; i < EFD * F; i += K5_THREADS) Wes[i] = We[i];
    for (int i = tid; i < F; i += K5_THREADS) bsum[i] = b[i] + be[i];
    __syncthreads();

    float4* xw4 = xs + warp * (K5_RPW * 32);
    const float* aggE = (const float*)g_aggE4;

    int nGroups = (N + K5_RPW - 1) / K5_RPW;
    for (int g = blockIdx.x * K5W + warp; g < nGroups;
         g += gridDim.x * K5W) {
        int row0 = g * K5_RPW;
        int nr = N - row0; if (nr > K5_RPW) nr = K5_RPW;
        #pragma unroll
        for (int r = 0; r < K5_RPW; r++) {
            int row = row0 + (r < nr ? r : 0);
            xw4[r * 32 + lane] = g_aggX[(long)row * 32 + lane];
        }
        __syncwarp();

        unsigned long long a01[K5_RPW], a23[K5_RPW];
        #pragma unroll
        for (int r = 0; r < K5_RPW; r++) { a01[r] = 0ULL; a23[r] = 0ULL; }

        #pragma unroll 2
        for (int kb = 0; kb < F; kb += 4) {
            ulonglong2 w0 = Wp[(kb + 0) * 32 + lane];
            ulonglong2 w1 = Wp[(kb + 1) * 32 + lane];
            ulonglong2 w2 = Wp[(kb + 2) * 32 + lane];
            ulonglong2 w3 = Wp[(kb + 3) * 32 + lane];
            #pragma unroll
            for (int r = 0; r < K5_RPW; r++) {
                float4 xv = xw4[r * 32 + (kb >> 2)];
                unsigned long long x0, x1, x2, x3;
                PACK_F32X2(x0, xv.x, xv.x);
                PACK_F32X2(x1, xv.y, xv.y);
                PACK_F32X2(x2, xv.z, xv.z);
                PACK_F32X2(x3, xv.w, xv.w);
                FMA_F32X2(a01[r], x0, w0.x, a01[r]);
                FMA_F32X2(a23[r], x0, w0.y, a23[r]);
                FMA_F32X2(a01[r], x1, w1.x, a01[r]);
                FMA_F32X2(a23[r], x1, w1.y, a23[r]);
                FMA_F32X2(a01[r], x2, w2.x, a01[r]);
                FMA_F32X2(a23[r], x2, w2.y, a23[r]);
                FMA_F32X2(a01[r], x3, w3.x, a01[r]);
                FMA_F32X2(a23[r], x3, w3.y, a23[r]);
            }
        }

        float4 b4 = ((const float4*)bsum)[lane];
        for (int r = 0; r < nr; r++) {
            int row = row0 + r;
            float deg = (float)(g_rowend[row] - g_rowptr[row]);
            float4 o;
            UNPACK_F32X2(o.x, o.y, a01[r]);
            UNPACK_F32X2(o.z, o.w, a23[r]);
            o.x = fmaf(deg, b4.x, o.x);
            o.y = fmaf(deg, b4.y, o.y);
            o.z = fmaf(deg, b4.z, o.z);
            o.w = fmaf(deg, b4.w, o.w);
            #pragma unroll
            for (int k = 0; k < EFD; k++) {
                float ek = aggE[row * 8 + k];
                float4 w4 = ((const float4*)(Wes + (k << 7)))[lane];
                o.x = fmaf(ek, w4.x, o.x);
                o.y = fmaf(ek, w4.y, o.y);
                o.z = fmaf(ek, w4.z, o.z);
                o.w = fmaf(ek, w4.w, o.w);
            }
            o.x = fmaxf(o.x, 0.f); o.y = fmaxf(o.y, 0.f);
            o.z = fmaxf(o.z, 0.f); o.w = fmaxf(o.w, 0.f);
            ((float4*)out)[(long)row * 32 + lane] = o;
            if (lane < 2) g_aggE4[row * 2 + lane] =
                make_float4(0.f, 0.f, 0.f, 0.f);
        }
        __syncwarp();
    }
}

// ---------------------------------------------------------------------------
extern "C" void kernel_launch(void* const* d_in, const int* in_sizes, int n_in,
                              void* d_out, int out_size) {
    const float* X  = (const float*)d_in[0];
    const void*  EI = d_in[1];
    const float* EF = (const float*)d_in[2];
    const float* W  = (const float*)d_in[3];
    const float* b  = (const float*)d_in[4];
    const float* We = (const float*)d_in[5];
    const float* be = (const float*)d_in[6];
    float* out = (float*)d_out;

    int N = in_sizes[0] / F;
    int E = in_sizes[2] / EFD;
    int B = (N + SCAN_T - 1) / SCAN_T;

    cudaFuncSetAttribute(k5_final, cudaFuncAttributeMaxDynamicSharedMemorySize,
                         K5_SMEM);

    k1_decode_hist<<<(E + 255) / 256, 256>>>(EI, EF, N, E);
    k2_scan<<<B, SCAN_T>>>(N);
    k3_scatter<<<(E + 2047) / 2048, 256>>>(E);
    k4_aggregate<<<(N * 32 + 255) / 256, 256>>>((const ulonglong2*)X, N);
    k5_final<<<K5_BLOCKS, K5_THREADS, K5_SMEM>>>((const float4*)W, b, We, be,
                                                 out, N);
}

// round 15
// speedup vs baseline: 1.0270x; 1.0270x over previous
#include <cuda_runtime.h>
#include <cuda_bf16.h>

#define NMAX 50000
#define EMAX 800000
#define F 128
#define EFD 6
#define SCAN_T 256

// ---- packed dual-fp32 ops (Blackwell f32x2) --------------------------------
#define PACK_F32X2(d, a, b) \
    asm("mov.b64 %0, {%1, %2};" : "=l"(d) : "f"(a), "f"(b))
#define FMA_F32X2(d, a, b, c) \
    asm("fma.rn.f32x2 %0, %1, %2, %3;" : "=l"(d) : "l"(a), "l"(b), "l"(c))
#define ADD_F32X2(d, a, b) \
    asm("add.rn.f32x2 %0, %1, %2;" : "=l"(d) : "l"(a), "l"(b))
#define UNPACK_F32X2(lo, hi, v) \
    asm("mov.b64 {%0, %1}, %2;" : "=f"(lo), "=f"(hi) : "l"(v))

// ---------------- device scratch ----------------
__device__ int    g_counts[NMAX];
__device__ int    g_cursor[NMAX];
__device__ int    g_rowptr[NMAX];     // region start (NOT globally monotonic)
__device__ int    g_rowend[NMAX];     // region end
__device__ int    g_src[EMAX];
__device__ int    g_dst[EMAX];
__device__ int    g_edges[EMAX];      // src only
__device__ float4 g_aggX[NMAX * (F / 4)];
__device__ float4 g_aggE4[NMAX * 2];  // padded 8 floats/node; re-zeroed by k5
__device__ int    g_total;            // tile-base allocator (reset in k1a)

// ---- shared helper: is the index buffer int64? (first-128-words probe) -----
__device__ __forceinline__ int probe_is64(const void* ei, int N, int E,
                                          int lane) {
    const long long* p = (const long long*)ei;
    long long nwords = (long long)E * 2;
    int bad = 0;
    #pragma unroll
    for (int j = 0; j < 4; j++) {
        long long idx = lane + j * 32;
        if (idx < nwords) {
            long long v = p[idx];
            if (v < 0 || v >= (long long)N) bad = 1;
        }
    }
    unsigned m = __ballot_sync(0xffffffffu, bad);
    return (m == 0u) ? 1 : 0;
}

// ---------------- K1a: decode + histogram (critical path) -------------------
__global__ void __launch_bounds__(256)
k1a_decode_hist(const void* __restrict__ ei, int N, int E) {
    __shared__ int s_is64;
    int t = threadIdx.x;
    if (t < 32) {
        int r = probe_is64(ei, N, E, t);
        if (t == 0) s_is64 = r;
    }
    __syncthreads();

    int e = blockIdx.x * blockDim.x + t;
    if (blockIdx.x == 0 && t == 0) g_total = 0;
    if (e >= E) return;
    int s, d;
    if (s_is64) {
        const longlong2* p = (const longlong2*)ei;
        longlong2 v = p[e];
        s = (int)v.x; d = (int)v.y;
    } else {
        const int2* p = (const int2*)ei;
        int2 v = p[e];
        s = v.x; d = v.y;
    }
    g_src[e] = s;
    g_dst[e] = d;
    atomicAdd(&g_counts[d], 1);
}

// ---------------- K1b: eF vector-atomic aggregation (side branch) -----------
__global__ void __launch_bounds__(256)
k1b_aggE(const void* __restrict__ ei, const float* __restrict__ eF,
         int N, int E) {
    __shared__ int s_is64;
    int t = threadIdx.x;
    if (t < 32) {
        int r = probe_is64(ei, N, E, t);
        if (t == 0) s_is64 = r;
    }
    __syncthreads();

    int e = blockIdx.x * blockDim.x + t;
    if (e >= E) return;
    int d;
    if (s_is64) {
        const long long* p = (const long long*)ei;
        d = (int)p[2 * e + 1];
    } else {
        const int* p = (const int*)ei;
        d = p[2 * e + 1];
    }
    const float2* ef2 = (const float2*)(eF + (long)e * EFD);
    float2 f0 = ef2[0], f1 = ef2[1], f2 = ef2[2];
    float* base = (float*)&g_aggE4[d * 2];
    atomicAdd((float4*)base, make_float4(f0.x, f0.y, f1.x, f1.y));
    atomicAdd((float2*)(base + 4), f2);
}

// ---------------- K2: single-kernel scan (atomic tile base) + re-zero -------
__global__ void __launch_bounds__(SCAN_T)
k2_scan(int N) {
    __shared__ int ws[8];
    __shared__ int s_base;
    int t = threadIdx.x, lane = t & 31, wid = t >> 5;
    int i = blockIdx.x * SCAN_T + t;
    int v = (i < N) ? g_counts[i] : 0;

    int x = v;
    #pragma unroll
    for (int o = 1; o < 32; o <<= 1) {
        int y = __shfl_up_sync(0xffffffffu, x, o);
        if (lane >= o) x += y;
    }
    if (lane == 31) ws[wid] = x;
    __syncthreads();
    if (wid == 0 && lane < 8) {
        int y = ws[lane];
        #pragma unroll
        for (int o = 1; o < 8; o <<= 1) {
            int z = __shfl_up_sync(0x000000ffu, y, o);
            if (lane >= o) y += z;
        }
        ws[lane] = y;
    }
    __syncthreads();
    int incl = x + (wid > 0 ? ws[wid - 1] : 0);

    if (t == 0) s_base = atomicAdd(&g_total, ws[7]);
    __syncthreads();

    if (i < N) {
        int start = s_base + incl - v;
        g_rowptr[i] = start;
        g_rowend[i] = start + v;
        g_cursor[i] = start;
        g_counts[i] = 0;
    }
}

// ---------------- K3: scatter src into CSR slots (MLP=8) --------------------
__global__ void __launch_bounds__(256)
k3_scatter(int E) {
    int e0 = (blockIdx.x * blockDim.x + threadIdx.x) * 8;
    int d[8], s[8];
    #pragma unroll
    for (int j = 0; j < 8; j++) {
        int e = e0 + j;
        if (e < E) { d[j] = g_dst[e]; s[j] = g_src[e]; }
    }
    #pragma unroll
    for (int j = 0; j < 8; j++) {
        int e = e0 + j;
        if (e < E) {
            int p = atomicAdd(&g_cursor[d[j]], 1);
            g_edges[p] = s[j];
        }
    }
}

// ---------------- K4: warp-per-node aggregation (dual acc chains) -----------
__global__ void __launch_bounds__(256)
k4_aggregate(const ulonglong2* __restrict__ X2, int N) {
    int gwarp = (blockIdx.x * blockDim.x + threadIdx.x) >> 5;
    int lane  = threadIdx.x & 31;
    if (gwarp >= N) return;
    int v = gwarp;
    int s0 = g_rowptr[v], s1 = g_rowend[v];
    unsigned long long a01a = 0ULL, a23a = 0ULL;   // even edges
    unsigned long long a01b = 0ULL, a23b = 0ULL;   // odd edges
    for (int base = s0; base < s1; base += 32) {
        int cnt = s1 - base; if (cnt > 32) cnt = 32;
        int sc = g_edges[base + (lane < cnt ? lane : 0)];   // coalesced chunk
        for (int j = 0; j < cnt; j += 16) {
            #pragma unroll
            for (int u = 0; u < 16; u++) {
                if (j + u < cnt) {  // uniform across warp
                    int sj = __shfl_sync(0xffffffffu, sc, j + u);
                    ulonglong2 xv = X2[(long)sj * 32 + lane];
                    if (u & 1) {
                        ADD_F32X2(a01b, a01b, xv.x);
                        ADD_F32X2(a23b, a23b, xv.y);
                    } else {
                        ADD_F32X2(a01a, a01a, xv.x);
                        ADD_F32X2(a23a, a23a, xv.y);
                    }
                }
            }
        }
    }
    ADD_F32X2(a01a, a01a, a01b);
    ADD_F32X2(a23a, a23a, a23b);
    ulonglong2 outv; outv.x = a01a; outv.y = a23a;
    *(ulonglong2*)&g_aggX[(long)v * 32 + lane] = outv;
}

// ---------------- K5: persistent f32x2 GEMM (round-12 shape) ----------------
#define K5_THREADS 512
#define K5W (K5_THREADS / 32)   // 16 warps
#define K5_RPW 8
#define K5_SMEM (F * 32 * 16 + EFD * F * 4 + F * 4 + K5W * K5_RPW * 32 * 16)

__global__ void __launch_bounds__(K5_THREADS)
k5_final(const float4* __restrict__ W4, const float* __restrict__ b,
         const float* __restrict__ We, const float* __restrict__ be,
         float* __restrict__ out, int N) {
    extern __shared__ char smem[];
    ulonglong2* Wp   = (ulonglong2*)smem;
    float*      Wes  = (float*)(smem + F * 32 * 16);
    float*      bsum = Wes + EFD * F;
    float4*     xs   = (float4*)(bsum + F);

    int tid = threadIdx.x, warp = tid >> 5, lane = tid & 31;

    for (int idx = tid; idx < F * 32; idx += K5_THREADS) {
        float4 w4 = __ldg(&W4[idx]);
        ulonglong2 p;
        PACK_F32X2(p.x, w4.x, w4.y);
        PACK_F32X2(p.y, w4.z, w4.w);
        Wp[idx] = p;
    }
    for (int i = tid; i < EFD * F; i += K5_THREADS) Wes[i] = We[i];
    for (int i = tid; i < F; i += K5_THREADS) bsum[i] = b[i] + be[i];
    __syncthreads();

    float4* xw4 = xs + warp * (K5_RPW * 32);
    const float* aggE = (const float*)g_aggE4;

    int nGroups = (N + K5_RPW - 1) / K5_RPW;
    for (int g = blockIdx.x * K5W + warp; g < nGroups; g += gridDim.x * K5W) {
        int row0 = g * K5_RPW;
        int nr = N - row0; if (nr > K5_RPW) nr = K5_RPW;
        #pragma unroll
        for (int r = 0; r < K5_RPW; r++) {
            int row = row0 + (r < nr ? r : 0);
            xw4[r * 32 + lane] = g_aggX[(long)row * 32 + lane];
        }
        __syncwarp();

        unsigned long long a01[K5_RPW], a23[K5_RPW];
        #pragma unroll
        for (int r = 0; r < K5_RPW; r++) { a01[r] = 0ULL; a23[r] = 0ULL; }

        #pragma unroll 2
        for (int kb = 0; kb < F; kb += 4) {
            ulonglong2 w0 = Wp[(kb + 0) * 32 + lane];
            ulonglong2 w1 = Wp[(kb + 1) * 32 + lane];
            ulonglong2 w2 = Wp[(kb + 2) * 32 + lane];
            ulonglong2 w3 = Wp[(kb + 3) * 32 + lane];
            #pragma unroll
            for (int r = 0; r < K5_RPW; r++) {
                float4 xv = xw4[r * 32 + (kb >> 2)];
                unsigned long long x0, x1, x2, x3;
                PACK_F32X2(x0, xv.x, xv.x);
                PACK_F32X2(x1, xv.y, xv.y);
                PACK_F32X2(x2, xv.z, xv.z);
                PACK_F32X2(x3, xv.w, xv.w);
                FMA_F32X2(a01[r], x0, w0.x, a01[r]);
                FMA_F32X2(a23[r], x0, w0.y, a23[r]);
                FMA_F32X2(a01[r], x1, w1.x, a01[r]);
                FMA_F32X2(a23[r], x1, w1.y, a23[r]);
                FMA_F32X2(a01[r], x2, w2.x, a01[r]);
                FMA_F32X2(a23[r], x2, w2.y, a23[r]);
                FMA_F32X2(a01[r], x3, w3.x, a01[r]);
                FMA_F32X2(a23[r], x3, w3.y, a23[r]);
            }
        }

        float4 b4 = ((const float4*)bsum)[lane];
        for (int r = 0; r < nr; r++) {
            int row = row0 + r;
            float deg = (float)(g_rowend[row] - g_rowptr[row]);
            float4 o;
            UNPACK_F32X2(o.x, o.y, a01[r]);
            UNPACK_F32X2(o.z, o.w, a23[r]);
            o.x = fmaf(deg, b4.x, o.x);
            o.y = fmaf(deg, b4.y, o.y);
            o.z = fmaf(deg, b4.z, o.z);
            o.w = fmaf(deg, b4.w, o.w);
            #pragma unroll
            for (int k = 0; k < EFD; k++) {
                float ek = aggE[row * 8 + k];
                float4 w4 = ((const float4*)(Wes + (k << 7)))[lane];
                o.x = fmaf(ek, w4.x, o.x);
                o.y = fmaf(ek, w4.y, o.y);
                o.z = fmaf(ek, w4.z, o.z);
                o.w = fmaf(ek, w4.w, o.w);
            }
            o.x = fmaxf(o.x, 0.f); o.y = fmaxf(o.y, 0.f);
            o.z = fmaxf(o.z, 0.f); o.w = fmaxf(o.w, 0.f);
            ((float4*)out)[(long)row * 32 + lane] = o;
            if (lane < 2) g_aggE4[row * 2 + lane] =
                make_float4(0.f, 0.f, 0.f, 0.f);
        }
        __syncwarp();
    }
}

// ---------------------------------------------------------------------------
extern "C" void kernel_launch(void* const* d_in, const int* in_sizes, int n_in,
                              void* d_out, int out_size) {
    const float* X  = (const float*)d_in[0];
    const void*  EI = d_in[1];
    const float* EF = (const float*)d_in[2];
    const float* W  = (const float*)d_in[3];
    const float* b  = (const float*)d_in[4];
    const float* We = (const float*)d_in[5];
    const float* be = (const float*)d_in[6];
    float* out = (float*)d_out;

    int N = in_sizes[0] / F;
    int E = in_sizes[2] / EFD;
    int B = (N + SCAN_T - 1) / SCAN_T;

    // one-time host-handle setup (no device memory involved; device work is
    // identical on every call)
    static cudaStream_t s2 = nullptr;
    static cudaEvent_t evFork = nullptr, evJoin = nullptr;
    if (s2 == nullptr) {
        cudaStreamCreateWithFlags(&s2, cudaStreamNonBlocking);
        cudaEventCreateWithFlags(&evFork, cudaEventDisableTiming);
        cudaEventCreateWithFlags(&evJoin, cudaEventDisableTiming);
        cudaFuncSetAttribute(k5_final,
                             cudaFuncAttributeMaxDynamicSharedMemorySize,
                             K5_SMEM);
    }

    // fork: eF aggregation runs concurrently with the CSR-build critical path
    cudaEventRecord(evFork, 0);
    cudaStreamWaitEvent(s2, evFork, 0);
    k1b_aggE<<<(E + 255) / 256, 256, 0, s2>>>(EI, EF, N, E);
    cudaEventRecord(evJoin, s2);

    // critical path (legacy stream)
    k1a_decode_hist<<<(E + 255) / 256, 256>>>(EI, N, E);
    k2_scan<<<B, SCAN_T>>>(N);
    k3_scatter<<<(E + 2047) / 2048, 256>>>(E);
    k4_aggregate<<<(N * 32 + 255) / 256, 256>>>((const ulonglong2*)X, N);

    // join: k5 needs aggE from the side branch
    cudaStreamWaitEvent(0, evJoin, 0);
    k5_final<<<148, K5_THREADS, K5_SMEM>>>((const float4*)W, b, We, be,
                                           out, N);
}

// round 16
// speedup vs baseline: 1.0472x; 1.0196x over previous
#include <cuda_runtime.h>
#include <cuda_bf16.h>

#define NMAX 50000
#define EMAX 800000
#define F 128
#define EFD 6
#define SCAN_T 256

// ---- packed dual-fp32 ops (Blackwell f32x2) --------------------------------
#define PACK_F32X2(d, a, b) \
    asm("mov.b64 %0, {%1, %2};" : "=l"(d) : "f"(a), "f"(b))
#define FMA_F32X2(d, a, b, c) \
    asm("fma.rn.f32x2 %0, %1, %2, %3;" : "=l"(d) : "l"(a), "l"(b), "l"(c))
#define ADD_F32X2(d, a, b) \
    asm("add.rn.f32x2 %0, %1, %2;" : "=l"(d) : "l"(a), "l"(b))
#define UNPACK_F32X2(lo, hi, v) \
    asm("mov.b64 {%0, %1}, %2;" : "=f"(lo), "=f"(hi) : "l"(v))

// ---------------- device scratch ----------------
__device__ int    g_counts[NMAX];
__device__ int    g_cursor[NMAX];
__device__ int    g_rowptr[NMAX];     // region start (NOT globally monotonic)
__device__ int    g_rowend[NMAX];     // region end
__device__ int    g_src[EMAX];
__device__ int    g_dst[EMAX];
__device__ int    g_edges[EMAX];      // src only
__device__ float4 g_aggX[NMAX * (F / 4)];
__device__ float4 g_aggE4[NMAX * 2];  // padded 8 floats/node; re-zeroed by k5
__device__ int    g_total;            // tile-base allocator (reset in k1)

// ---------------- K1: decode + histogram + eF vector-atomic aggregation -----
__global__ void __launch_bounds__(256)
k1_decode_hist(const void* __restrict__ ei, const float* __restrict__ eF,
               int N, int E) {
    __shared__ int s_is64;
    int t = threadIdx.x;
    if (t < 32) {
        const long long* p = (const long long*)ei;
        long long nwords = (long long)E * 2;
        int bad = 0;
        #pragma unroll
        for (int j = 0; j < 4; j++) {
            long long idx = t + j * 32;
            if (idx < nwords) {
                long long v = p[idx];
                if (v < 0 || v >= (long long)N) bad = 1;
            }
        }
        unsigned m = __ballot_sync(0xffffffffu, bad);
        if (t == 0) s_is64 = (m == 0u) ? 1 : 0;
    }
    __syncthreads();

    int e = blockIdx.x * blockDim.x + t;
    if (blockIdx.x == 0 && t == 0) g_total = 0;
    if (e >= E) return;
    int s, d;
    if (s_is64) {
        const longlong2* p = (const longlong2*)ei;
        longlong2 v = p[e];
        s = (int)v.x; d = (int)v.y;
    } else {
        const int2* p = (const int2*)ei;
        int2 v = p[e];
        s = v.x; d = v.y;
    }
    g_src[e] = s;
    g_dst[e] = d;
    atomicAdd(&g_counts[d], 1);

    const float2* ef2 = (const float2*)(eF + (long)e * EFD);
    float2 f0 = ef2[0], f1 = ef2[1], f2 = ef2[2];
    float* base = (float*)&g_aggE4[d * 2];
    atomicAdd((float4*)base, make_float4(f0.x, f0.y, f1.x, f1.y));
    atomicAdd((float2*)(base + 4), f2);
}

// ---------------- K2: single-kernel scan (atomic tile base) + re-zero -------
__global__ void __launch_bounds__(SCAN_T)
k2_scan(int N) {
    __shared__ int ws[8];
    __shared__ int s_base;
    int t = threadIdx.x, lane = t & 31, wid = t >> 5;
    int i = blockIdx.x * SCAN_T + t;
    int v = (i < N) ? g_counts[i] : 0;

    int x = v;
    #pragma unroll
    for (int o = 1; o < 32; o <<= 1) {
        int y = __shfl_up_sync(0xffffffffu, x, o);
        if (lane >= o) x += y;
    }
    if (lane == 31) ws[wid] = x;
    __syncthreads();
    if (wid == 0 && lane < 8) {
        int y = ws[lane];
        #pragma unroll
        for (int o = 1; o < 8; o <<= 1) {
            int z = __shfl_up_sync(0x000000ffu, y, o);
            if (lane >= o) y += z;
        }
        ws[lane] = y;
    }
    __syncthreads();
    int incl = x + (wid > 0 ? ws[wid - 1] : 0);

    if (t == 0) s_base = atomicAdd(&g_total, ws[7]);
    __syncthreads();

    if (i < N) {
        int start = s_base + incl - v;
        g_rowptr[i] = start;
        g_rowend[i] = start + v;
        g_cursor[i] = start;
        g_counts[i] = 0;
    }
}

// ---------------- K3: scatter src into CSR slots (MLP=2, big grid) ----------
__global__ void __launch_bounds__(256)
k3_scatter(int E) {
    int e0 = (blockIdx.x * blockDim.x + threadIdx.x) * 2;
    int d0 = 0, d1 = 0, s0 = 0, s1 = 0;
    if (e0 < E)     { d0 = g_dst[e0];     s0 = g_src[e0]; }
    if (e0 + 1 < E) { d1 = g_dst[e0 + 1]; s1 = g_src[e0 + 1]; }
    if (e0 < E) {
        int p = atomicAdd(&g_cursor[d0], 1);
        g_edges[p] = s0;
    }
    if (e0 + 1 < E) {
        int p = atomicAdd(&g_cursor[d1], 1);
        g_edges[p] = s1;
    }
}

// ---------------- K4: warp-per-node aggregation (dual acc chains) -----------
__global__ void __launch_bounds__(256)
k4_aggregate(const ulonglong2* __restrict__ X2, int N) {
    int gwarp = (blockIdx.x * blockDim.x + threadIdx.x) >> 5;
    int lane  = threadIdx.x & 31;
    if (gwarp >= N) return;
    int v = gwarp;
    int s0 = g_rowptr[v], s1 = g_rowend[v];
    unsigned long long a01a = 0ULL, a23a = 0ULL;   // even edges
    unsigned long long a01b = 0ULL, a23b = 0ULL;   // odd edges
    for (int base = s0; base < s1; base += 32) {
        int cnt = s1 - base; if (cnt > 32) cnt = 32;
        int sc = g_edges[base + (lane < cnt ? lane : 0)];   // coalesced chunk
        for (int j = 0; j < cnt; j += 16) {
            #pragma unroll
            for (int u = 0; u < 16; u++) {
                if (j + u < cnt) {  // uniform across warp
                    int sj = __shfl_sync(0xffffffffu, sc, j + u);
                    ulonglong2 xv = X2[(long)sj * 32 + lane];
                    if (u & 1) {
                        ADD_F32X2(a01b, a01b, xv.x);
                        ADD_F32X2(a23b, a23b, xv.y);
                    } else {
                        ADD_F32X2(a01a, a01a, xv.x);
                        ADD_F32X2(a23a, a23a, xv.y);
                    }
                }
            }
        }
    }
    ADD_F32X2(a01a, a01a, a01b);
    ADD_F32X2(a23a, a23a, a23b);
    ulonglong2 outv; outv.x = a01a; outv.y = a23a;
    *(ulonglong2*)&g_aggX[(long)v * 32 + lane] = outv;
}

// ---------------- K5: persistent f32x2 GEMM (round-12 shape) ----------------
#define K5_THREADS 512
#define K5W (K5_THREADS / 32)   // 16 warps
#define K5_RPW 8
#define K5_SMEM (F * 32 * 16 + EFD * F * 4 + F * 4 + K5W * K5_RPW * 32 * 16)

__global__ void __launch_bounds__(K5_THREADS)
k5_final(const float4* __restrict__ W4, const float* __restrict__ b,
         const float* __restrict__ We, const float* __restrict__ be,
         float* __restrict__ out, int N) {
    extern __shared__ char smem[];
    ulonglong2* Wp   = (ulonglong2*)smem;
    float*      Wes  = (float*)(smem + F * 32 * 16);
    float*      bsum = Wes + EFD * F;
    float4*     xs   = (float4*)(bsum + F);

    int tid = threadIdx.x, warp = tid >> 5, lane = tid & 31;

    for (int idx = tid; idx < F * 32; idx += K5_THREADS) {
        float4 w4 = __ldg(&W4[idx]);
        ulonglong2 p;
        PACK_F32X2(p.x, w4.x, w4.y);
        PACK_F32X2(p.y, w4.z, w4.w);
        Wp[idx] = p;
    }
    for (int i = tid; i < EFD * F; i += K5_THREADS) Wes[i] = We[i];
    for (int i = tid; i < F; i += K5_THREADS) bsum[i] = b[i] + be[i];
    __syncthreads();

    float4* xw4 = xs + warp * (K5_RPW * 32);
    const float* aggE = (const float*)g_aggE4;

    int nGroups = (N + K5_RPW - 1) / K5_RPW;
    for (int g = blockIdx.x * K5W + warp; g < nGroups; g += gridDim.x * K5W) {
        int row0 = g * K5_RPW;
        int nr = N - row0; if (nr > K5_RPW) nr = K5_RPW;
        #pragma unroll
        for (int r = 0; r < K5_RPW; r++) {
            int row = row0 + (r < nr ? r : 0);
            xw4[r * 32 + lane] = g_aggX[(long)row * 32 + lane];
        }
        __syncwarp();

        unsigned long long a01[K5_RPW], a23[K5_RPW];
        #pragma unroll
        for (int r = 0; r < K5_RPW; r++) { a01[r] = 0ULL; a23[r] = 0ULL; }

        #pragma unroll 2
        for (int kb = 0; kb < F; kb += 4) {
            ulonglong2 w0 = Wp[(kb + 0) * 32 + lane];
            ulonglong2 w1 = Wp[(kb + 1) * 32 + lane];
            ulonglong2 w2 = Wp[(kb + 2) * 32 + lane];
            ulonglong2 w3 = Wp[(kb + 3) * 32 + lane];
            #pragma unroll
            for (int r = 0; r < K5_RPW; r++) {
                float4 xv = xw4[r * 32 + (kb >> 2)];
                unsigned long long x0, x1, x2, x3;
                PACK_F32X2(x0, xv.x, xv.x);
                PACK_F32X2(x1, xv.y, xv.y);
                PACK_F32X2(x2, xv.z, xv.z);
                PACK_F32X2(x3, xv.w, xv.w);
                FMA_F32X2(a01[r], x0, w0.x, a01[r]);
                FMA_F32X2(a23[r], x0, w0.y, a23[r]);
                FMA_F32X2(a01[r], x1, w1.x, a01[r]);
                FMA_F32X2(a23[r], x1, w1.y, a23[r]);
                FMA_F32X2(a01[r], x2, w2.x, a01[r]);
                FMA_F32X2(a23[r], x2, w2.y, a23[r]);
                FMA_F32X2(a01[r], x3, w3.x, a01[r]);
                FMA_F32X2(a23[r], x3, w3.y, a23[r]);
            }
        }

        float4 b4 = ((const float4*)bsum)[lane];
        for (int r = 0; r < nr; r++) {
            int row = row0 + r;
            float deg = (float)(g_rowend[row] - g_rowptr[row]);
            float4 o;
            UNPACK_F32X2(o.x, o.y, a01[r]);
            UNPACK_F32X2(o.z, o.w, a23[r]);
            o.x = fmaf(deg, b4.x, o.x);
            o.y = fmaf(deg, b4.y, o.y);
            o.z = fmaf(deg, b4.z, o.z);
            o.w = fmaf(deg, b4.w, o.w);
            #pragma unroll
            for (int k = 0; k < EFD; k++) {
                float ek = aggE[row * 8 + k];
                float4 w4 = ((const float4*)(Wes + (k << 7)))[lane];
                o.x = fmaf(ek, w4.x, o.x);
                o.y = fmaf(ek, w4.y, o.y);
                o.z = fmaf(ek, w4.z, o.z);
                o.w = fmaf(ek, w4.w, o.w);
            }
            o.x = fmaxf(o.x, 0.f); o.y = fmaxf(o.y, 0.f);
            o.z = fmaxf(o.z, 0.f); o.w = fmaxf(o.w, 0.f);
            ((float4*)out)[(long)row * 32 + lane] = o;
            if (lane < 2) g_aggE4[row * 2 + lane] =
                make_float4(0.f, 0.f, 0.f, 0.f);
        }
        __syncwarp();
    }
}

// ---------------------------------------------------------------------------
extern "C" void kernel_launch(void* const* d_in, const int* in_sizes, int n_in,
                              void* d_out, int out_size) {
    const float* X  = (const float*)d_in[0];
    const void*  EI = d_in[1];
    const float* EF = (const float*)d_in[2];
    const float* W  = (const float*)d_in[3];
    const float* b  = (const float*)d_in[4];
    const float* We = (const float*)d_in[5];
    const float* be = (const float*)d_in[6];
    float* out = (float*)d_out;

    int N = in_sizes[0] / F;
    int E = in_sizes[2] / EFD;
    int B = (N + SCAN_T - 1) / SCAN_T;

    cudaFuncSetAttribute(k5_final, cudaFuncAttributeMaxDynamicSharedMemorySize,
                         K5_SMEM);

    k1_decode_hist<<<(E + 255) / 256, 256>>>(EI, EF, N, E);
    k2_scan<<<B, SCAN_T>>>(N);
    k3_scatter<<<(E + 511) / 512, 256>>>(E);
    k4_aggregate<<<(N * 32 + 255) / 256, 256>>>((const ulonglong2*)X, N);
    k5_final<<<148, K5_THREADS, K5_SMEM>>>((const float4*)W, b, We, be,
                                           out, N);
}